// round 1
// baseline (speedup 1.0000x reference)
#include <cuda_runtime.h>
#include <cuda_bf16.h>
#include <cstdint>

// Problem constants (fixed shapes for this bench instance)
#define BB 2
#define NN 50
#define CC 80
#define MM 28
#define HH 800
#define WW 1333
#define HW (HH * WW)                   // 1,066,400 (divisible by 4)
#define MASK_ELEMS ((long long)BB * NN * HW)  // 106,640,000

// Scratch (device globals only; no allocation allowed)
__device__ int    g_selOff[BB * NN];        // offset into mask_outs for selected class mask
__device__ float4 g_bounds[BB * NN];        // conservative pixel-space bbox {xlo, xhi, ylo, yhi}
__device__ __align__(4) unsigned char g_winner[BB * HW]; // 255 = no winner

// ---------------------------------------------------------------------------
// Prep: per-instance selected-mask offset + conservative coverage bounds.
// Coverage region in exact math: ix in [-1, 28)  <=>  xc in
// [x0 - (0.5/28)*bw, x1 + (0.5/28)*bw]. We use 0.05*bw + 1 margin (superset).
// ---------------------------------------------------------------------------
__global__ void det2mask_prep(const float* __restrict__ boxes,
                              const int* __restrict__ cls)
{
    int i = threadIdx.x;
    if (i >= BB * NN) return;
    float x0 = boxes[i * 4 + 0];
    float y0 = boxes[i * 4 + 1];
    float x1 = boxes[i * 4 + 2];
    float y1 = boxes[i * 4 + 3];
    int c = cls[i];
    g_selOff[i] = (i * CC + c) * (MM * MM);
    float bw = x1 - x0, bh = y1 - y0;
    g_bounds[i] = make_float4(x0 - 0.05f * bw - 1.0f,
                              x1 + 0.05f * bw + 1.0f,
                              y0 - 0.05f * bh - 1.0f,
                              y1 + 0.05f * bh + 1.0f);
}

// ---------------------------------------------------------------------------
// Phase 1: per-pixel winner. Exactly reproduces the reference float sequence
// (plain IEEE mul/add/sub/div, no FMA contraction) so the >=0.5 threshold is
// bit-identical.
// ---------------------------------------------------------------------------
__global__ void det2mask_winner(const float* __restrict__ mask_outs,
                                const float* __restrict__ boxes,
                                const float* __restrict__ scores)
{
    int x = blockIdx.x * blockDim.x + threadIdx.x;
    int y = blockIdx.y;
    int b = blockIdx.z;
    if (x >= WW) return;

    float xc = (float)x + 0.5f;
    float yc = (float)y + 0.5f;

    int   best = 255;
    float bestScore = -1.0f;  // scores are in [0,1)

    #pragma unroll 1
    for (int n = 0; n < NN; n++) {
        int i = b * NN + n;
        float4 bd = g_bounds[i];
        if (xc < bd.x || xc > bd.y || yc < bd.z || yc > bd.w) continue;

        float x0 = boxes[i * 4 + 0];
        float y0 = boxes[i * 4 + 1];
        float x1 = boxes[i * 4 + 2];
        float y1 = boxes[i * 4 + 3];

        // iy = ((((yc - y0)/(y1 - y0))*2 - 1 + 1)*28 - 1)/2  (reference op order)
        float ty  = __fdiv_rn(__fsub_rn(yc, y0), __fsub_rn(y1, y0));
        float gy  = __fsub_rn(__fmul_rn(ty, 2.0f), 1.0f);
        float iy  = __fmul_rn(__fsub_rn(__fmul_rn(__fadd_rn(gy, 1.0f), 28.0f), 1.0f), 0.5f);
        float iy0f = floorf(iy);
        float wy  = __fsub_rn(iy, iy0f);

        float tx  = __fdiv_rn(__fsub_rn(xc, x0), __fsub_rn(x1, x0));
        float gx  = __fsub_rn(__fmul_rn(tx, 2.0f), 1.0f);
        float ix  = __fmul_rn(__fsub_rn(__fmul_rn(__fadd_rn(gx, 1.0f), 28.0f), 1.0f), 0.5f);
        float ix0f = floorf(ix);
        float wx  = __fsub_rn(ix, ix0f);

        int iy0 = (int)iy0f;
        int ix0 = (int)ix0f;
        if (iy0 < -1 || iy0 > MM - 1 || ix0 < -1 || ix0 > MM - 1) continue;

        const float* mp = mask_outs + g_selOff[i];
        int r0 = iy0, r1 = iy0 + 1;
        int c0 = ix0, c1 = ix0 + 1;
        // r0 <= 27 and c0 <= 27 guaranteed by range check; r1/c1 >= 0 guaranteed.
        float v00 = (r0 >= 0 && c0 >= 0)          ? mp[r0 * MM + c0] : 0.0f;
        float v01 = (r0 >= 0 && c1 <= MM - 1)     ? mp[r0 * MM + c1] : 0.0f;
        float v10 = (r1 <= MM - 1 && c0 >= 0)     ? mp[r1 * MM + c0] : 0.0f;
        float v11 = (r1 <= MM - 1 && c1 <= MM - 1)? mp[r1 * MM + c1] : 0.0f;

        float omwy = __fsub_rn(1.0f, wy);
        float rr0  = __fadd_rn(__fmul_rn(v00, omwy), __fmul_rn(v10, wy));
        float rr1  = __fadd_rn(__fmul_rn(v01, omwy), __fmul_rn(v11, wy));
        float omwx = __fsub_rn(1.0f, wx);
        float soft = __fadd_rn(__fmul_rn(rr0, omwx), __fmul_rn(rr1, wx));

        if (soft >= 0.5f) {
            float s = scores[i];
            if (s > bestScore) { bestScore = s; best = n; }  // strict > : ties keep lower n
        }
    }
    g_winner[b * HW + y * WW + x] = (unsigned char)best;
}

// ---------------------------------------------------------------------------
// Phase 2: broadcast winner into the 106.6M-element mask output.
// float4 stores (HW % 4 == 0 so every plane base and every quad is aligned).
// ---------------------------------------------------------------------------
__global__ void det2mask_write(float* __restrict__ out)
{
    int bn = blockIdx.y;                 // 0..99  (b*50 + n)
    int p  = (blockIdx.x * blockDim.x + threadIdx.x) * 4;
    if (p >= HW) return;
    int b = bn / NN;
    unsigned char n = (unsigned char)(bn % NN);

    uchar4 w = *reinterpret_cast<const uchar4*>(&g_winner[b * HW + p]);
    float4 o;
    o.x = (w.x == n) ? 1.0f : 0.0f;
    o.y = (w.y == n) ? 1.0f : 0.0f;
    o.z = (w.z == n) ? 1.0f : 0.0f;
    o.w = (w.w == n) ? 1.0f : 0.0f;
    *reinterpret_cast<float4*>(out + (long long)bn * HW + p) = o;
}

// Optional tail: scores then class_ids appended as float32.
__global__ void det2mask_tail(const float* __restrict__ scores,
                              const int* __restrict__ cls,
                              float* __restrict__ out)
{
    int i = threadIdx.x;
    if (i >= BB * NN) return;
    out[MASK_ELEMS + i] = scores[i];
    out[MASK_ELEMS + BB * NN + i] = (float)cls[i];
}

extern "C" void kernel_launch(void* const* d_in, const int* in_sizes, int n_in,
                              void* d_out, int out_size)
{
    const float* mask_outs = (const float*)d_in[0];
    const float* boxes     = (const float*)d_in[1];
    const float* scores    = (const float*)d_in[2];
    const int*   cls       = (const int*)d_in[3];
    float* out = (float*)d_out;

    det2mask_prep<<<1, 128>>>(boxes, cls);

    dim3 gw((WW + 255) / 256, HH, BB);
    det2mask_winner<<<gw, 256>>>(mask_outs, boxes, scores);

    dim3 gm((HW / 4 + 255) / 256, BB * NN);
    det2mask_write<<<gm, 256>>>(out);

    if ((long long)out_size >= MASK_ELEMS + 2 * BB * NN) {
        det2mask_tail<<<1, 128>>>(scores, cls, out);
    }
}

// round 2
// speedup vs baseline: 1.2002x; 1.2002x over previous
#include <cuda_runtime.h>
#include <cuda_bf16.h>
#include <cstdint>

#define BB 2
#define NN 50
#define CC 80
#define MM 28
#define HH 800
#define WW 1333
#define HW (HH * WW)                          // 1,066,400 (divisible by 8)
#define MASK_ELEMS ((long long)BB * NN * HW)  // 106,640,000

// Scratch: per-instance data, sorted by descending score within each batch
// (stable: ties keep lower original index). Index = b*NN + rank.
__device__ float4 g_sbox[BB * NN];     // {x0,y0,x1,y1}
__device__ float4 g_sbounds[BB * NN];  // conservative pixel bbox {xlo,xhi,ylo,yhi}
__device__ int2   g_sinfo[BB * NN];    // {selOff into mask_outs, original n}
__device__ __align__(8) unsigned char g_winner[BB * HW]; // 255 = no winner

// ---------------------------------------------------------------------------
// Prep: stable descending-score sort (O(N^2) rank, N=50) + per-instance data.
// Also writes the scores/class_ids tail of the output.
// ---------------------------------------------------------------------------
__global__ void det2mask_prep(const float* __restrict__ boxes,
                              const float* __restrict__ scores,
                              const int* __restrict__ cls,
                              float* __restrict__ out, int writeTail)
{
    int i = threadIdx.x;
    if (i >= BB * NN) return;
    int b = i / NN, n = i - b * NN;
    float s = scores[i];
    int rank = 0;
    #pragma unroll 1
    for (int j = 0; j < NN; j++) {
        float sj = scores[b * NN + j];
        rank += (sj > s) || (sj == s && j < n);
    }
    int pos = b * NN + rank;
    float x0 = boxes[i * 4 + 0], y0 = boxes[i * 4 + 1];
    float x1 = boxes[i * 4 + 2], y1 = boxes[i * 4 + 3];
    g_sbox[pos] = make_float4(x0, y0, x1, y1);
    float bw = x1 - x0, bh = y1 - y0;
    g_sbounds[pos] = make_float4(x0 - 0.05f * bw - 1.0f,
                                 x1 + 0.05f * bw + 1.0f,
                                 y0 - 0.05f * bh - 1.0f,
                                 y1 + 0.05f * bh + 1.0f);
    g_sinfo[pos] = make_int2((i * CC + cls[i]) * (MM * MM), n);
    if (writeTail) {
        out[MASK_ELEMS + i] = s;
        out[MASK_ELEMS + BB * NN + i] = (float)cls[i];
    }
}

// ---------------------------------------------------------------------------
// Phase 1: per-pixel winner with tile-level culling + first-hit early exit.
// Block = 32x8 pixel tile. Intersecting instances are ballot-compacted into
// shared memory preserving sorted (descending-score) order, so the first
// soft>=0.5 hit IS the reference winner.
// Bilinear math is the bit-exact reference op sequence (no FMA contraction).
// ---------------------------------------------------------------------------
__global__ void det2mask_winner(const float* __restrict__ mask_outs)
{
    int b   = blockIdx.z;
    int tx0 = blockIdx.x * 32;
    int ty0 = blockIdx.y * 8;
    int lx  = threadIdx.x, ly = threadIdx.y;
    int flat = ly * 32 + lx;

    __shared__ unsigned char s_list[NN];
    __shared__ unsigned s_ballot[2];

    // Tile pixel-center extents
    float txmin = (float)tx0 + 0.5f, txmax = (float)tx0 + 31.5f;
    float tymin = (float)ty0 + 0.5f, tymax = (float)ty0 + 7.5f;

    if (flat < 64) {
        bool hit = false;
        if (flat < NN) {
            float4 bd = g_sbounds[b * NN + flat];
            hit = (txmax >= bd.x) && (txmin <= bd.y) &&
                  (tymax >= bd.z) && (tymin <= bd.w);
        }
        unsigned m = __ballot_sync(0xffffffffu, hit);
        if ((flat & 31) == 0) s_ballot[flat >> 5] = m;
    }
    __syncthreads();
    if (flat < 64) {
        unsigned m = s_ballot[flat >> 5];
        if ((m >> (flat & 31)) & 1u) {
            int pos = ((flat >= 32) ? __popc(s_ballot[0]) : 0)
                      + __popc(m & ((1u << (flat & 31)) - 1u));
            s_list[pos] = (unsigned char)flat;
        }
    }
    __syncthreads();
    int cnt = __popc(s_ballot[0]) + __popc(s_ballot[1]);

    int x = tx0 + lx, y = ty0 + ly;
    if (x >= WW) return;

    float xc = (float)x + 0.5f;
    float yc = (float)y + 0.5f;
    int best = 255;

    #pragma unroll 1
    for (int k = 0; k < cnt; k++) {
        int i = b * NN + s_list[k];
        float4 bd = g_sbounds[i];
        if (xc < bd.x || xc > bd.y || yc < bd.z || yc > bd.w) continue;

        float4 bx = g_sbox[i];

        float ty_  = __fdiv_rn(__fsub_rn(yc, bx.y), __fsub_rn(bx.w, bx.y));
        float gy   = __fsub_rn(__fmul_rn(ty_, 2.0f), 1.0f);
        float iy   = __fmul_rn(__fsub_rn(__fmul_rn(__fadd_rn(gy, 1.0f), 28.0f), 1.0f), 0.5f);
        float iy0f = floorf(iy);
        float wy   = __fsub_rn(iy, iy0f);

        float tx_  = __fdiv_rn(__fsub_rn(xc, bx.x), __fsub_rn(bx.z, bx.x));
        float gx   = __fsub_rn(__fmul_rn(tx_, 2.0f), 1.0f);
        float ix   = __fmul_rn(__fsub_rn(__fmul_rn(__fadd_rn(gx, 1.0f), 28.0f), 1.0f), 0.5f);
        float ix0f = floorf(ix);
        float wx   = __fsub_rn(ix, ix0f);

        int iy0 = (int)iy0f;
        int ix0 = (int)ix0f;
        if (iy0 < -1 || iy0 > MM - 1 || ix0 < -1 || ix0 > MM - 1) continue;

        int2 info = g_sinfo[i];
        const float* mp = mask_outs + info.x;
        int r0 = iy0, r1 = iy0 + 1;
        int c0 = ix0, c1 = ix0 + 1;
        float v00 = (r0 >= 0 && c0 >= 0)           ? mp[r0 * MM + c0] : 0.0f;
        float v01 = (r0 >= 0 && c1 <= MM - 1)      ? mp[r0 * MM + c1] : 0.0f;
        float v10 = (r1 <= MM - 1 && c0 >= 0)      ? mp[r1 * MM + c0] : 0.0f;
        float v11 = (r1 <= MM - 1 && c1 <= MM - 1) ? mp[r1 * MM + c1] : 0.0f;

        float omwy = __fsub_rn(1.0f, wy);
        float rr0  = __fadd_rn(__fmul_rn(v00, omwy), __fmul_rn(v10, wy));
        float rr1  = __fadd_rn(__fmul_rn(v01, omwy), __fmul_rn(v11, wy));
        float omwx = __fsub_rn(1.0f, wx);
        float soft = __fadd_rn(__fmul_rn(rr0, omwx), __fmul_rn(rr1, wx));

        if (soft >= 0.5f) {
            int2 inf = g_sinfo[i];
            best = inf.y;           // first hit in sorted order wins
            break;
        }
    }
    g_winner[b * HW + y * WW + x] = (unsigned char)best;
}

// ---------------------------------------------------------------------------
// Phase 2: broadcast winner into the 106.6M-float output.
// 8 pixels / thread, 2x float4 streaming stores. HW % 8 == 0.
// ---------------------------------------------------------------------------
__global__ void det2mask_write(float* __restrict__ out)
{
    int bn = blockIdx.y;                              // 0..99
    int p  = (blockIdx.x * blockDim.x + threadIdx.x) * 8;
    if (p >= HW) return;
    int b = (bn >= NN) ? 1 : 0;
    unsigned n = (unsigned)(bn - b * NN);

    uint2 w = *reinterpret_cast<const uint2*>(&g_winner[b * HW + p]);
    float4 o0, o1;
    o0.x = (( w.x        & 0xffu) == n) ? 1.0f : 0.0f;
    o0.y = (((w.x >> 8)  & 0xffu) == n) ? 1.0f : 0.0f;
    o0.z = (((w.x >> 16) & 0xffu) == n) ? 1.0f : 0.0f;
    o0.w = (( w.x >> 24        ) == n) ? 1.0f : 0.0f;
    o1.x = (( w.y        & 0xffu) == n) ? 1.0f : 0.0f;
    o1.y = (((w.y >> 8)  & 0xffu) == n) ? 1.0f : 0.0f;
    o1.z = (((w.y >> 16) & 0xffu) == n) ? 1.0f : 0.0f;
    o1.w = (( w.y >> 24        ) == n) ? 1.0f : 0.0f;

    float* dst = out + (long long)bn * HW + p;
    __stcs(reinterpret_cast<float4*>(dst),     o0);
    __stcs(reinterpret_cast<float4*>(dst) + 1, o1);
}

extern "C" void kernel_launch(void* const* d_in, const int* in_sizes, int n_in,
                              void* d_out, int out_size)
{
    const float* mask_outs = (const float*)d_in[0];
    const float* boxes     = (const float*)d_in[1];
    const float* scores    = (const float*)d_in[2];
    const int*   cls       = (const int*)d_in[3];
    float* out = (float*)d_out;

    int writeTail = ((long long)out_size >= MASK_ELEMS + 2 * BB * NN) ? 1 : 0;
    det2mask_prep<<<1, 128>>>(boxes, scores, cls, out, writeTail);

    dim3 gw((WW + 31) / 32, HH / 8, BB);
    det2mask_winner<<<gw, dim3(32, 8)>>>(mask_outs);

    dim3 gm((HW / 8 + 255) / 256, BB * NN);
    det2mask_write<<<gm, 256>>>(out);
}

// round 3
// speedup vs baseline: 1.5926x; 1.3270x over previous
#include <cuda_runtime.h>
#include <cuda_bf16.h>
#include <cstdint>

#define BB 2
#define NN 50
#define CC 80
#define MM 28
#define HH 800
#define WW 1333
#define HW (HH * WW)                          // 1,066,400 (divisible by 4)
#define MASK_ELEMS ((long long)BB * NN * HW)  // 106,640,000
#define CHUNK 2048                            // pixels per block (mult of 4)
#define NCHUNK ((HW + CHUNK - 1) / CHUNK)     // 521

// ---------------------------------------------------------------------------
// Single fused kernel.
// Each block: one 2048-pixel flat chunk of one batch, all 50 output planes.
//  1. Build score-sorted instance table in shared (stable desc sort, N=50).
//  2. Y-range cull instances against the chunk's row span (ballot compact,
//     order preserving -> first soft>=0.5 hit IS the reference winner).
//  3. Each thread computes winner bytes for its 8 pixels (bit-exact
//     reference float op sequence, no FMA contraction).
//  4. Zero-blast its 2 float4 groups across all 50 planes (aligned STG.128).
//  5. Overwrite its winner pixels with 1.0f (same-thread program order
//     guarantees the 1.0 lands after the zero).
// ---------------------------------------------------------------------------
__global__ __launch_bounds__(256) void det2mask_fused(
    const float* __restrict__ mask_outs,
    const float* __restrict__ boxes,
    const float* __restrict__ scores,
    const int*   __restrict__ cls,
    float* __restrict__ out,
    int writeTail)
{
    const int b  = blockIdx.y;
    const int t  = threadIdx.x;
    const int base_p = blockIdx.x * CHUNK;

    __shared__ float4 s_box[NN];   // sorted {x0,y0,x1,y1}
    __shared__ float4 s_bnd[NN];   // sorted conservative pixel bounds
    __shared__ int2   s_inf[NN];   // sorted {mask offset, original n}
    __shared__ unsigned char s_list[NN];
    __shared__ unsigned s_ballot[2];

    // --- 1. sorted table -------------------------------------------------
    if (t < NN) {
        int i = b * NN + t;
        float s = scores[i];
        int rank = 0;
        #pragma unroll 1
        for (int j = 0; j < NN; j++) {
            float sj = scores[b * NN + j];
            rank += (sj > s) || (sj == s && j < t);
        }
        float x0 = boxes[i * 4 + 0], y0 = boxes[i * 4 + 1];
        float x1 = boxes[i * 4 + 2], y1 = boxes[i * 4 + 3];
        s_box[rank] = make_float4(x0, y0, x1, y1);
        float bw = x1 - x0, bh = y1 - y0;
        s_bnd[rank] = make_float4(x0 - 0.05f * bw - 1.0f,
                                  x1 + 0.05f * bw + 1.0f,
                                  y0 - 0.05f * bh - 1.0f,
                                  y1 + 0.05f * bh + 1.0f);
        s_inf[rank] = make_int2((i * CC + cls[i]) * (MM * MM), t);
    }
    // optional tail while we're here
    if (writeTail && blockIdx.x == 0 && b == 0 && t < BB * NN) {
        out[MASK_ELEMS + t] = scores[t];
        out[MASK_ELEMS + BB * NN + t] = (float)cls[t];
    }
    __syncthreads();

    // --- 2. y-range cull (chunk spans rows y0r..y1r) ---------------------
    int pend = base_p + CHUNK; if (pend > HW) pend = HW;
    int y0r = base_p / WW;
    int y1r = (pend - 1) / WW;
    float tymin = (float)y0r + 0.5f, tymax = (float)y1r + 0.5f;

    if (t < 64) {
        bool hit = false;
        if (t < NN) {
            float4 bd = s_bnd[t];
            hit = (tymax >= bd.z) && (tymin <= bd.w);
        }
        unsigned m = __ballot_sync(0xffffffffu, hit);
        if ((t & 31) == 0) s_ballot[t >> 5] = m;
    }
    __syncthreads();
    if (t < 64) {
        unsigned m = s_ballot[t >> 5];
        if ((m >> (t & 31)) & 1u) {
            int pos = ((t >= 32) ? __popc(s_ballot[0]) : 0)
                      + __popc(m & ((1u << (t & 31)) - 1u));
            s_list[pos] = (unsigned char)t;
        }
    }
    __syncthreads();
    const int cnt = __popc(s_ballot[0]) + __popc(s_ballot[1]);

    // --- 3. winner bytes for this thread's 8 pixels ----------------------
    // groups g = k*256 + t (k=0,1), pixels p = base_p + g*4 + j
    unsigned wreg[2];
    #pragma unroll
    for (int k = 0; k < 2; k++) {
        unsigned wv = 0xffffffffu;                  // 255 = no winner
        int p0 = base_p + (k * 256 + t) * 4;
        if (p0 < HW && cnt > 0) {
            #pragma unroll
            for (int j = 0; j < 4; j++) {
                int p = p0 + j;
                int y = p / WW;
                int x = p - y * WW;
                float xc = (float)x + 0.5f;
                float yc = (float)y + 0.5f;
                int best = 255;
                #pragma unroll 1
                for (int kk = 0; kk < cnt; kk++) {
                    int si = s_list[kk];
                    float4 bd = s_bnd[si];
                    if (xc < bd.x || xc > bd.y || yc < bd.z || yc > bd.w) continue;
                    float4 bx = s_box[si];

                    float ty_  = __fdiv_rn(__fsub_rn(yc, bx.y), __fsub_rn(bx.w, bx.y));
                    float gy   = __fsub_rn(__fmul_rn(ty_, 2.0f), 1.0f);
                    float iy   = __fmul_rn(__fsub_rn(__fmul_rn(__fadd_rn(gy, 1.0f), 28.0f), 1.0f), 0.5f);
                    float iy0f = floorf(iy);
                    float wy   = __fsub_rn(iy, iy0f);

                    float tx_  = __fdiv_rn(__fsub_rn(xc, bx.x), __fsub_rn(bx.z, bx.x));
                    float gx   = __fsub_rn(__fmul_rn(tx_, 2.0f), 1.0f);
                    float ix   = __fmul_rn(__fsub_rn(__fmul_rn(__fadd_rn(gx, 1.0f), 28.0f), 1.0f), 0.5f);
                    float ix0f = floorf(ix);
                    float wx   = __fsub_rn(ix, ix0f);

                    int iy0 = (int)iy0f;
                    int ix0 = (int)ix0f;
                    if (iy0 < -1 || iy0 > MM - 1 || ix0 < -1 || ix0 > MM - 1) continue;

                    const float* mp = mask_outs + s_inf[si].x;
                    int r0 = iy0, r1 = iy0 + 1;
                    int c0 = ix0, c1 = ix0 + 1;
                    float v00 = (r0 >= 0 && c0 >= 0)           ? mp[r0 * MM + c0] : 0.0f;
                    float v01 = (r0 >= 0 && c1 <= MM - 1)      ? mp[r0 * MM + c1] : 0.0f;
                    float v10 = (r1 <= MM - 1 && c0 >= 0)      ? mp[r1 * MM + c0] : 0.0f;
                    float v11 = (r1 <= MM - 1 && c1 <= MM - 1) ? mp[r1 * MM + c1] : 0.0f;

                    float omwy = __fsub_rn(1.0f, wy);
                    float rr0  = __fadd_rn(__fmul_rn(v00, omwy), __fmul_rn(v10, wy));
                    float rr1  = __fadd_rn(__fmul_rn(v01, omwy), __fmul_rn(v11, wy));
                    float omwx = __fsub_rn(1.0f, wx);
                    float soft = __fadd_rn(__fmul_rn(rr0, omwx), __fmul_rn(rr1, wx));

                    if (soft >= 0.5f) { best = s_inf[si].y; break; }
                }
                wv = (wv & ~(0xffu << (j * 8))) | ((unsigned)best << (j * 8));
            }
        }
        wreg[k] = wv;
    }

    // --- 4. zero-blast all 50 planes (aligned float4 streaming stores) ---
    float* outb = out + b * (NN * HW) + base_p;
    const float4 z4 = make_float4(0.f, 0.f, 0.f, 0.f);
    const int g0 = t, g1 = 256 + t;
    const bool ok0 = (base_p + g0 * 4) < HW;
    const bool ok1 = (base_p + g1 * 4) < HW;
    #pragma unroll 2
    for (int n = 0; n < NN; n++) {
        float4* pl = reinterpret_cast<float4*>(outb + n * HW);
        if (ok0) __stcs(pl + g0, z4);
        if (ok1) __stcs(pl + g1, z4);
    }

    // --- 5. overwrite winner pixels with 1.0 (same thread => ordered) ----
    #pragma unroll
    for (int k = 0; k < 2; k++) {
        unsigned wv = wreg[k];
        int p0 = base_p + (k * 256 + t) * 4;
        #pragma unroll
        for (int j = 0; j < 4; j++) {
            unsigned n = (wv >> (j * 8)) & 0xffu;
            if (n != 0xffu) {
                out[b * (NN * HW) + (int)n * HW + p0 + j] = 1.0f;
            }
        }
    }
}

extern "C" void kernel_launch(void* const* d_in, const int* in_sizes, int n_in,
                              void* d_out, int out_size)
{
    const float* mask_outs = (const float*)d_in[0];
    const float* boxes     = (const float*)d_in[1];
    const float* scores    = (const float*)d_in[2];
    const int*   cls       = (const int*)d_in[3];
    float* out = (float*)d_out;

    int writeTail = ((long long)out_size >= MASK_ELEMS + 2 * BB * NN) ? 1 : 0;
    dim3 grid(NCHUNK, BB);
    det2mask_fused<<<grid, 256>>>(mask_outs, boxes, scores, cls, out, writeTail);
}